// round 2
// baseline (speedup 1.0000x reference)
#include <cuda_runtime.h>
#include <stdint.h>

#define BATCH   512
#define EMB     512
#define NCLS    100

// Scratch (no allocations allowed in kernel_launch).
// Two K-slices so the GEMM can use 128 blocks (one wave) without atomics.
__device__ float g_D[2][BATCH * BATCH];
__device__ float g_partial[BATCH];

// ---------------------------------------------------------------------------
// Kernel 1: D_z = X[:, z*256:(z+1)*256] @ X[:, z*256:(z+1)*256]^T
// 64x64 tile, 256 threads, 4x4 micro-tile per thread, BK=16.
// ---------------------------------------------------------------------------
#define BM 64
#define BN 64
#define BK 16
#define KSPLIT 2
#define KSLICE (EMB / KSPLIT)   // 256

__global__ __launch_bounds__(256) void gemm_xxT(const float* __restrict__ X) {
    __shared__ float As[BM][BK + 1];
    __shared__ float Bs[BN][BK + 1];

    const int tid = threadIdx.x;
    const int tx = tid & 15;        // 0..15 -> column group
    const int ty = tid >> 4;        // 0..15 -> row group
    const int bx = blockIdx.x;      // col tile
    const int by = blockIdx.y;      // row tile
    const int bz = blockIdx.z;      // K slice
    const int k0 = bz * KSLICE;

    float acc[4][4] = {};

    for (int kt = 0; kt < KSLICE; kt += BK) {
        // Load 64x16 A tile and 64x16 B tile (1024 floats each, 4 per thread)
        #pragma unroll
        for (int l = 0; l < 4; l++) {
            int idx = tid + l * 256;
            int r = idx >> 4;       // 0..63
            int c = idx & 15;       // 0..15
            As[r][c] = X[(by * BM + r) * EMB + k0 + kt + c];
            Bs[r][c] = X[(bx * BN + r) * EMB + k0 + kt + c];
        }
        __syncthreads();

        #pragma unroll
        for (int k = 0; k < BK; k++) {
            float a[4], b[4];
            #pragma unroll
            for (int i = 0; i < 4; i++) a[i] = As[ty * 4 + i][k];
            #pragma unroll
            for (int j = 0; j < 4; j++) b[j] = Bs[tx * 4 + j][k];
            #pragma unroll
            for (int i = 0; i < 4; i++)
                #pragma unroll
                for (int j = 0; j < 4; j++)
                    acc[i][j] = fmaf(a[i], b[j], acc[i][j]);
        }
        __syncthreads();
    }

    float* Dz = g_D[bz];
    #pragma unroll
    for (int i = 0; i < 4; i++) {
        int row = by * BM + ty * 4 + i;
        #pragma unroll
        for (int j = 0; j < 4; j++) {
            Dz[row * BATCH + bx * BN + tx * 4 + j] = acc[i][j];
        }
    }
}

// ---------------------------------------------------------------------------
// Kernel 2: per-anchor hinge sum.
// Block i handles anchor i:
//   sum_{j pos} sum_{k neg} max(D[i,j] - D[i,k] + mu[labels[i]], 0)
// pos: j != i, labels[j]==labels[i];  neg: labels[k]!=labels[i]
// NOTE: labels passed as int32 (JAX int64 request downcasts to int32 without
// x64 mode; reading int64 here ran off the end of the buffer in R1).
// ---------------------------------------------------------------------------
__global__ __launch_bounds__(256) void row_loss(const int* __restrict__ labels,
                                                const float* __restrict__ mu) {
    const int i = blockIdx.x;
    const int tid = threadIdx.x;

    __shared__ float rowD[BATCH];
    __shared__ int   lab[BATCH];
    __shared__ float posv[BATCH];
    __shared__ int   npos_s;
    __shared__ float red[256];

    for (int t = tid; t < BATCH; t += 256) {
        rowD[t] = g_D[0][i * BATCH + t] + g_D[1][i * BATCH + t];
        lab[t]  = labels[t];
    }
    __syncthreads();

    const int li = lab[i];

    // Deterministic positive collection (order fixed -> bitwise-stable result)
    if (tid == 0) {
        int np = 0;
        for (int t = 0; t < BATCH; t++) {
            if (t != i && lab[t] == li) posv[np++] = rowD[t];
        }
        npos_s = np;
    }
    __syncthreads();

    const int   np  = npos_s;
    const float mui = mu[li];

    float s = 0.f;
    for (int k = tid; k < BATCH; k += 256) {
        if (lab[k] != li) {
            float base = mui - rowD[k];
            for (int p = 0; p < np; p++) {
                s += fmaxf(posv[p] + base, 0.f);
            }
        }
    }

    red[tid] = s;
    __syncthreads();
    #pragma unroll
    for (int o = 128; o > 0; o >>= 1) {
        if (tid < o) red[tid] += red[tid + o];
        __syncthreads();
    }
    if (tid == 0) g_partial[i] = red[0];
}

// ---------------------------------------------------------------------------
// Kernel 3: final deterministic reduction + margin regularizers.
// ---------------------------------------------------------------------------
__global__ __launch_bounds__(BATCH) void finalize(const float* __restrict__ mu,
                                                  const float* __restrict__ nv,
                                                  float* __restrict__ out) {
    __shared__ float red[BATCH];
    const int tid = threadIdx.x;

    float v = g_partial[tid];
    if (tid < NCLS) v -= (mu[tid] + nv[tid]) * (1.0f / NCLS);
    red[tid] = v;
    __syncthreads();

    #pragma unroll
    for (int o = 256; o > 0; o >>= 1) {
        if (tid < o) red[tid] += red[tid + o];
        __syncthreads();
    }
    if (tid == 0) out[0] = red[0];
}

// ---------------------------------------------------------------------------
extern "C" void kernel_launch(void* const* d_in, const int* in_sizes, int n_in,
                              void* d_out, int out_size) {
    const float* X      = (const float*)d_in[0];
    const int*   labels = (const int*)d_in[1];
    const float* mu     = (const float*)d_in[2];
    const float* nv     = (const float*)d_in[3];
    float*       out    = (float*)d_out;

    dim3 ggrid(BATCH / BN, BATCH / BM, KSPLIT);   // 8 x 8 x 2 = 128 blocks
    gemm_xxT<<<ggrid, 256>>>(X);
    row_loss<<<BATCH, 256>>>(labels, mu);
    finalize<<<1, BATCH>>>(mu, nv, out);
}

// round 3
// speedup vs baseline: 2.0076x; 2.0076x over previous
#include <cuda_runtime.h>
#include <stdint.h>

#define BATCH   512
#define EMB     512
#define NCLS    100

#define BM 128
#define BN 128
#define BK 16
#define KSPLIT 8
#define KSLICE (EMB / KSPLIT)   // 64

// Scratch: 8 K-slices of D so the GEMM gets 128 CTAs without atomics.
__device__ float g_D[KSPLIT][BATCH * BATCH];

// ---------------------------------------------------------------------------
// Kernel 1: D_z = X[:, z*64:(z+1)*64] @ X[:, ...]^T
// 128x128 tile, 256 threads, 8x8 micro-tile, BK=16, k-major smem + LDS.128.
// Block (0,0,0) thread 0 also seeds out[0] with the margin regularizer.
// ---------------------------------------------------------------------------
__global__ __launch_bounds__(256) void gemm_xxT(const float* __restrict__ X,
                                                const float* __restrict__ mu,
                                                const float* __restrict__ nv,
                                                float* __restrict__ out) {
    __shared__ float As[BK][BM];
    __shared__ float Bs[BK][BN];

    const int tid = threadIdx.x;
    const int bx = blockIdx.x;
    const int by = blockIdx.y;
    const int bz = blockIdx.z;
    const int k0 = bz * KSLICE;

    if (bx == 0 && by == 0 && bz == 0 && tid == 0) {
        float s = 0.f;
        for (int c = 0; c < NCLS; c++) s += mu[c] + nv[c];
        out[0] = -s * (1.0f / NCLS);
    }

    const int ty = tid >> 4;   // 0..15 -> 8-row group
    const int tx = tid & 15;   // 0..15 -> 8-col group

    float acc[8][8] = {};

    for (int kt = 0; kt < KSLICE; kt += BK) {
        // Load 128x16 A and B tiles as float4 (512 float4 each, 2/thread).
        #pragma unroll
        for (int l = 0; l < 2; l++) {
            int idx = tid + l * 256;    // 0..511
            int r   = idx >> 2;         // 0..127
            int c4  = idx & 3;          // 0..3  -> k-quad
            float4 va = *(const float4*)&X[(by * BM + r) * EMB + k0 + kt + c4 * 4];
            As[c4 * 4 + 0][r] = va.x; As[c4 * 4 + 1][r] = va.y;
            As[c4 * 4 + 2][r] = va.z; As[c4 * 4 + 3][r] = va.w;
            float4 vb = *(const float4*)&X[(bx * BN + r) * EMB + k0 + kt + c4 * 4];
            Bs[c4 * 4 + 0][r] = vb.x; Bs[c4 * 4 + 1][r] = vb.y;
            Bs[c4 * 4 + 2][r] = vb.z; Bs[c4 * 4 + 3][r] = vb.w;
        }
        __syncthreads();

        #pragma unroll
        for (int k = 0; k < BK; k++) {
            float a[8], b[8];
            *(float4*)&a[0] = *(const float4*)&As[k][ty * 8];
            *(float4*)&a[4] = *(const float4*)&As[k][ty * 8 + 4];
            *(float4*)&b[0] = *(const float4*)&Bs[k][tx * 8];
            *(float4*)&b[4] = *(const float4*)&Bs[k][tx * 8 + 4];
            #pragma unroll
            for (int i = 0; i < 8; i++)
                #pragma unroll
                for (int j = 0; j < 8; j++)
                    acc[i][j] = fmaf(a[i], b[j], acc[i][j]);
        }
        __syncthreads();
    }

    float* Dz = g_D[bz];
    #pragma unroll
    for (int i = 0; i < 8; i++) {
        int row = by * BM + ty * 8 + i;
        float* dst = &Dz[row * BATCH + bx * BN + tx * 8];
        *(float4*)&dst[0] = *(float4*)&acc[i][0];
        *(float4*)&dst[4] = *(float4*)&acc[i][4];
    }
}

// ---------------------------------------------------------------------------
// Kernel 2: per-anchor hinge sum, atomically accumulated into out[0].
// Ballot-based positive compaction (deterministic index order within block).
// ---------------------------------------------------------------------------
__global__ __launch_bounds__(256) void row_loss(const int* __restrict__ labels,
                                                const float* __restrict__ mu,
                                                float* __restrict__ out) {
    const int i   = blockIdx.x;
    const int tid = threadIdx.x;
    const int w    = tid >> 5;
    const int lane = tid & 31;

    __shared__ float rowD[BATCH];
    __shared__ int   lab[BATCH];
    __shared__ float posv[BATCH];
    __shared__ int   warpoff[8];
    __shared__ int   base_s;
    __shared__ float red[8];

    for (int t = tid; t < BATCH; t += 256) {
        lab[t] = labels[t];
        float s = 0.f;
        #pragma unroll
        for (int z = 0; z < KSPLIT; z++) s += g_D[z][i * BATCH + t];
        rowD[t] = s;
    }
    if (tid == 0) base_s = 0;
    __syncthreads();

    const int   li  = lab[i];
    const float mui = mu[li];

    // Compact positives in index order: two passes over t = p*256 + tid.
    #pragma unroll
    for (int p = 0; p < 2; p++) {
        int t = p * 256 + tid;
        bool pred = (t != i) && (lab[t] == li);
        unsigned m = __ballot_sync(0xffffffffu, pred);
        if (lane == 0) warpoff[w] = __popc(m);
        __syncthreads();
        if (tid == 0) {
            int off = base_s;
            for (int ww = 0; ww < 8; ww++) {
                int c = warpoff[ww];
                warpoff[ww] = off;
                off += c;
            }
            base_s = off;
        }
        __syncthreads();
        if (pred) {
            int pos = warpoff[w] + __popc(m & ((1u << lane) - 1u));
            posv[pos] = rowD[t];
        }
        __syncthreads();
    }

    const int np = base_s;

    float s = 0.f;
    for (int k = tid; k < BATCH; k += 256) {
        if (lab[k] != li) {
            float b = mui - rowD[k];
            for (int p = 0; p < np; p++)
                s += fmaxf(posv[p] + b, 0.f);
        }
    }

    // warp reduce, then cross-warp reduce, then one atomic per block
    #pragma unroll
    for (int o = 16; o > 0; o >>= 1) s += __shfl_xor_sync(0xffffffffu, s, o);
    if (lane == 0) red[w] = s;
    __syncthreads();
    if (w == 0) {
        float v = (lane < 8) ? red[lane] : 0.f;
        #pragma unroll
        for (int o = 4; o > 0; o >>= 1) v += __shfl_xor_sync(0xffffffffu, v, o);
        if (lane == 0) atomicAdd(out, v);
    }
}

// ---------------------------------------------------------------------------
extern "C" void kernel_launch(void* const* d_in, const int* in_sizes, int n_in,
                              void* d_out, int out_size) {
    const float* X      = (const float*)d_in[0];
    const int*   labels = (const int*)d_in[1];
    const float* mu     = (const float*)d_in[2];
    const float* nv     = (const float*)d_in[3];
    float*       out    = (float*)d_out;

    dim3 ggrid(BATCH / BN, BATCH / BM, KSPLIT);   // 4 x 4 x 8 = 128 blocks
    gemm_xxT<<<ggrid, 256>>>(X, mu, nv, out);
    row_loss<<<BATCH, 256>>>(labels, mu, out);
}

// round 4
// speedup vs baseline: 2.8488x; 1.4190x over previous
#include <cuda_runtime.h>
#include <stdint.h>

#define BATCH   512
#define EMB     512
#define NCLS    100

#define KSPLIT  4
#define KSLICE  (EMB / KSPLIT)   // 128
#define BM      64
#define BN      128
#define BK      32

// Scratch: 4 K-slices of D (GEMM gets 8x4x4 = 128 CTAs without atomics).
__device__ float g_D[KSPLIT][BATCH * BATCH];

__device__ __forceinline__ uint32_t f2tf32(float f) {
    uint32_t r;
    asm("cvt.rna.tf32.f32 %0, %1;" : "=r"(r) : "f"(f));
    return r;
}

// ---------------------------------------------------------------------------
// Kernel 1: tf32 tensor-core GEMM, D_z = X_slice @ X_slice^T.
// CTA tile 64x128, 8 warps (2x4), warp tile 32x32, mma.m16n8k8.tf32.
// Block (0,0,0) thread 0 seeds out[0] with the margin regularizer.
// ---------------------------------------------------------------------------
__global__ __launch_bounds__(256) void gemm_xxT_tc(const float* __restrict__ X,
                                                   const float* __restrict__ mu,
                                                   const float* __restrict__ nv,
                                                   float* __restrict__ out) {
    // stride 36 floats: bank = (4*group + tig) % 32 -> conflict-free frag loads,
    // and 36*4=144 bytes keeps float4 stores 16B-aligned.
    __shared__ uint32_t As[BM][36];
    __shared__ uint32_t Bs[BN][36];

    const int tid = threadIdx.x;
    const int bx = blockIdx.x;          // N tile (0..3)
    const int by = blockIdx.y;          // M tile (0..7)
    const int bz = blockIdx.z;          // K slice (0..3)
    const int k0 = bz * KSLICE;

    if (bx == 0 && by == 0 && bz == 0 && tid == 0) {
        float s = 0.f;
        for (int c = 0; c < NCLS; c++) s += mu[c] + nv[c];
        out[0] = -s * (1.0f / NCLS);
    }

    const int w    = tid >> 5;
    const int lane = tid & 31;
    const int g    = lane >> 2;      // group 0..7
    const int tig  = lane & 3;       // thread-in-group 0..3
    const int wm   = w & 1;          // warp m-tile (2 x 32 rows)
    const int wn   = w >> 1;         // warp n-tile (4 x 32 cols)

    float acc[2][4][4] = {};

    for (int kt = 0; kt < KSLICE; kt += BK) {
        // A tile: 64 rows x 32 k -> 512 float4, 2 per thread
        #pragma unroll
        for (int l = 0; l < 2; l++) {
            int idx = tid + l * 256;
            int r = idx >> 3, c4 = idx & 7;
            float4 v = *(const float4*)&X[(by * BM + r) * EMB + k0 + kt + c4 * 4];
            uint4 t; t.x = f2tf32(v.x); t.y = f2tf32(v.y); t.z = f2tf32(v.z); t.w = f2tf32(v.w);
            *(uint4*)&As[r][c4 * 4] = t;
        }
        // B tile: 128 rows (n) x 32 k -> 1024 float4, 4 per thread
        #pragma unroll
        for (int l = 0; l < 4; l++) {
            int idx = tid + l * 256;
            int r = idx >> 3, c4 = idx & 7;
            float4 v = *(const float4*)&X[(bx * BN + r) * EMB + k0 + kt + c4 * 4];
            uint4 t; t.x = f2tf32(v.x); t.y = f2tf32(v.y); t.z = f2tf32(v.z); t.w = f2tf32(v.w);
            *(uint4*)&Bs[r][c4 * 4] = t;
        }
        __syncthreads();

        #pragma unroll
        for (int kk = 0; kk < BK; kk += 8) {
            uint32_t a[2][4], b[4][2];
            #pragma unroll
            for (int mi = 0; mi < 2; mi++) {
                int r0 = wm * 32 + mi * 16;
                a[mi][0] = As[r0 + g    ][kk + tig];
                a[mi][1] = As[r0 + g + 8][kk + tig];
                a[mi][2] = As[r0 + g    ][kk + tig + 4];
                a[mi][3] = As[r0 + g + 8][kk + tig + 4];
            }
            #pragma unroll
            for (int ni = 0; ni < 4; ni++) {
                int n0 = wn * 32 + ni * 8;
                b[ni][0] = Bs[n0 + g][kk + tig];
                b[ni][1] = Bs[n0 + g][kk + tig + 4];
            }
            #pragma unroll
            for (int mi = 0; mi < 2; mi++)
                #pragma unroll
                for (int ni = 0; ni < 4; ni++) {
                    asm volatile(
                        "mma.sync.aligned.m16n8k8.row.col.f32.tf32.tf32.f32 "
                        "{%0,%1,%2,%3}, {%4,%5,%6,%7}, {%8,%9}, {%0,%1,%2,%3};"
                        : "+f"(acc[mi][ni][0]), "+f"(acc[mi][ni][1]),
                          "+f"(acc[mi][ni][2]), "+f"(acc[mi][ni][3])
                        : "r"(a[mi][0]), "r"(a[mi][1]), "r"(a[mi][2]), "r"(a[mi][3]),
                          "r"(b[ni][0]), "r"(b[ni][1]));
                }
        }
        __syncthreads();
    }

    // Epilogue: D fragment layout -> g_D[bz]
    float* Dz = g_D[bz];
    #pragma unroll
    for (int mi = 0; mi < 2; mi++) {
        #pragma unroll
        for (int ni = 0; ni < 4; ni++) {
            int r = by * BM + wm * 32 + mi * 16 + g;
            int c = bx * BN + wn * 32 + ni * 8 + 2 * tig;
            *(float2*)&Dz[r * BATCH + c]       = make_float2(acc[mi][ni][0], acc[mi][ni][1]);
            *(float2*)&Dz[(r + 8) * BATCH + c] = make_float2(acc[mi][ni][2], acc[mi][ni][3]);
        }
    }
}

// ---------------------------------------------------------------------------
// Kernel 2: per-anchor hinge sum, atomically accumulated into out[0].
// ---------------------------------------------------------------------------
__global__ __launch_bounds__(256) void row_loss(const int* __restrict__ labels,
                                                const float* __restrict__ mu,
                                                float* __restrict__ out) {
    const int i   = blockIdx.x;
    const int tid = threadIdx.x;
    const int w    = tid >> 5;
    const int lane = tid & 31;

    __shared__ float rowD[BATCH];
    __shared__ int   lab[BATCH];
    __shared__ float posv[BATCH];
    __shared__ int   warpoff[8];
    __shared__ int   base_s;
    __shared__ float red[8];

    for (int t = tid; t < BATCH; t += 256) {
        lab[t] = labels[t];
        float s = 0.f;
        #pragma unroll
        for (int z = 0; z < KSPLIT; z++) s += g_D[z][i * BATCH + t];
        rowD[t] = s;
    }
    if (tid == 0) base_s = 0;
    __syncthreads();

    const int   li  = lab[i];
    const float mui = mu[li];

    // Compact positives in index order (deterministic within block).
    #pragma unroll
    for (int p = 0; p < 2; p++) {
        int t = p * 256 + tid;
        bool pred = (t != i) && (lab[t] == li);
        unsigned m = __ballot_sync(0xffffffffu, pred);
        if (lane == 0) warpoff[w] = __popc(m);
        __syncthreads();
        if (tid == 0) {
            int off = base_s;
            for (int ww = 0; ww < 8; ww++) {
                int c = warpoff[ww];
                warpoff[ww] = off;
                off += c;
            }
            base_s = off;
        }
        __syncthreads();
        if (pred) {
            int pos = warpoff[w] + __popc(m & ((1u << lane) - 1u));
            posv[pos] = rowD[t];
        }
        __syncthreads();
    }

    const int np = base_s;

    float s = 0.f;
    for (int k = tid; k < BATCH; k += 256) {
        if (lab[k] != li) {
            float b = mui - rowD[k];
            for (int p = 0; p < np; p++)
                s += fmaxf(posv[p] + b, 0.f);
        }
    }

    #pragma unroll
    for (int o = 16; o > 0; o >>= 1) s += __shfl_xor_sync(0xffffffffu, s, o);
    if (lane == 0) red[w] = s;
    __syncthreads();
    if (w == 0) {
        float v = (lane < 8) ? red[lane] : 0.f;
        #pragma unroll
        for (int o = 4; o > 0; o >>= 1) v += __shfl_xor_sync(0xffffffffu, v, o);
        if (lane == 0) atomicAdd(out, v);
    }
}

// ---------------------------------------------------------------------------
extern "C" void kernel_launch(void* const* d_in, const int* in_sizes, int n_in,
                              void* d_out, int out_size) {
    const float* X      = (const float*)d_in[0];
    const int*   labels = (const int*)d_in[1];
    const float* mu     = (const float*)d_in[2];
    const float* nv     = (const float*)d_in[3];
    float*       out    = (float*)d_out;

    dim3 ggrid(BATCH / BN, BATCH / BM, KSPLIT);   // 4 x 8 x 4 = 128 CTAs
    gemm_xxT_tc<<<ggrid, 256>>>(X, mu, nv, out);
    row_loss<<<BATCH, 256>>>(labels, mu, out);
}